// round 10
// baseline (speedup 1.0000x reference)
#include <cuda_runtime.h>
#include <cuda_bf16.h>
#include <cstdint>

// Problem constants (match reference setup_inputs)
#define T_TABLES   8
#define N_ROWS     100000
#define EMB_D      128
#define N_BAGS_B   8192
#define BAG_SHIFT  13          // log2(N_BAGS_B)

#define CTAS_PER_SM 4
#define NUM_SMS     148
#define CTAS        (NUM_SMS * CTAS_PER_SM)   // 592  (measured best)
#define THREADS     256                       // 8 warps/CTA -> 32 warps/SM

// Persistent kernel: each warp grid-strides over bags (one warp per bag).
// Lane l owns floats [4l, 4l+4) of the D=128 row, so each row gather is a
// single fully-coalesced 512B warp transaction (LDG.E.128 x 32 lanes).
__global__ __launch_bounds__(THREADS, CTAS_PER_SM) void emb_bag_kernel(
    const int* __restrict__ indices,
    const int* __restrict__ offsets,
    const float* __restrict__ weights,
    float* __restrict__ out)
{
    const int lane        = threadIdx.x & 31;
    const int warp0       = (blockIdx.x * THREADS + threadIdx.x) >> 5;
    const int total_warps = (CTAS * THREADS) >> 5;   // 4736
    const int num_bags    = T_TABLES * N_BAGS_B;

    const char* __restrict__ wbytes =
        (const char*)weights + (unsigned)lane * 16u;

    int bag = warp0;
    if (bag >= num_bags) return;

    // Prefetch state for the first bag handled by this warp.
    int pf_start = __ldg(offsets + bag);
    int pf_end   = __ldg(offsets + bag + 1);
    int pf_idx   = (lane < pf_end - pf_start) ? __ldg(indices + pf_start + lane) : 0;

    while (bag < num_bags) {
        const int t     = bag >> BAG_SHIFT;          // table id
        const int b     = bag & (N_BAGS_B - 1);      // bag within table
        const int start = pf_start;
        const int end   = pf_end;
        int       myidx = pf_idx;

        // Issue next bag's index/offset loads early so their latency hides
        // under this bag's gather burst.
        const int next_bag = bag + total_warps;
        if (next_bag < num_bags) {
            pf_start = __ldg(offsets + next_bag);
            pf_end   = __ldg(offsets + next_bag + 1);
            pf_idx   = (lane < pf_end - pf_start) ? __ldg(indices + pf_start + lane) : 0;
        }

        // Table base: 64-bit once per bag; per-row offset is 32-bit (<51.2MB).
        const char* __restrict__ wbase =
            wbytes + (long long)t * (N_ROWS * EMB_D * 4ll);

        float4 acc = make_float4(0.f, 0.f, 0.f, 0.f);

        const int n0 = end - start;
        if (n0 == 32) {
            // Hot path: full 32-index bag, fully unrolled -> ptxas batches
            // ~14 independent LDG.E.128 per warp (latency fully hidden).
            #pragma unroll
            for (int j = 0; j < 32; ++j) {
                const unsigned r = (unsigned)__shfl_sync(0xffffffffu, myidx, j);
                const float4 v = __ldg((const float4*)(wbase + (r << 9)));
                acc.x += v.x; acc.y += v.y; acc.z += v.z; acc.w += v.w;
            }
        } else {
            // Generic path: bags longer/shorter than 32.
            int i = start;
            int cur = myidx;
            int n = min(32, end - i);
            while (n > 0) {
                for (int j = 0; j < n; ++j) {
                    const unsigned r = (unsigned)__shfl_sync(0xffffffffu, cur, j);
                    const float4 v = __ldg((const float4*)(wbase + (r << 9)));
                    acc.x += v.x; acc.y += v.y; acc.z += v.z; acc.w += v.w;
                }
                i += n;
                n = min(32, end - i);
                if (n > 0) cur = (lane < n) ? __ldg(indices + i + lane) : 0;
            }
        }

        // Output layout: [B, T*D] feature-concatenated: out[b, t*D + d].
        // Streaming store: zero-reuse output must not displace the active
        // weight-table window in L2.
        float4* __restrict__ o =
            (float4*)(out + ((long long)b * T_TABLES + t) * EMB_D);
        __stcs(o + lane, acc);

        bag = next_bag;
    }
}

extern "C" void kernel_launch(void* const* d_in, const int* in_sizes, int n_in,
                              void* d_out, int out_size)
{
    const int*   indices = (const int*)d_in[0];
    const int*   offsets = (const int*)d_in[1];
    const float* weights = (const float*)d_in[2];
    float*       out     = (float*)d_out;

    emb_bag_kernel<<<CTAS, THREADS>>>(indices, offsets, weights, out);
}

// round 12
// speedup vs baseline: 1.0105x; 1.0105x over previous
#include <cuda_runtime.h>
#include <cuda_bf16.h>
#include <cstdint>

// Problem constants (match reference setup_inputs)
#define T_TABLES   8
#define N_ROWS     100000
#define EMB_D      128
#define N_BAGS_B   8192
#define BAG_SHIFT  13          // log2(N_BAGS_B)

#define CTAS_PER_SM 2
#define NUM_SMS     148
#define CTAS        (NUM_SMS * CTAS_PER_SM)   // 296
#define THREADS     512                       // 16 warps/CTA -> 32 warps/SM

// Persistent kernel: each warp grid-strides over bags (one warp per bag).
// Lane l owns floats [4l, 4l+4) of the D=128 row, so each row gather is a
// single fully-coalesced 512B warp transaction (LDG.E.128 x 32 lanes).
__global__ __launch_bounds__(THREADS, CTAS_PER_SM) void emb_bag_kernel(
    const int* __restrict__ indices,
    const int* __restrict__ offsets,
    const float* __restrict__ weights,
    float* __restrict__ out)
{
    const int lane        = threadIdx.x & 31;
    const int warp0       = (blockIdx.x * THREADS + threadIdx.x) >> 5;
    const int total_warps = (CTAS * THREADS) >> 5;   // 4736 (same as best)
    const int num_bags    = T_TABLES * N_BAGS_B;

    const char* __restrict__ wbytes =
        (const char*)weights + (unsigned)lane * 16u;

    int bag = warp0;
    if (bag >= num_bags) return;

    // Prefetch state for the first bag handled by this warp.
    int pf_start = __ldg(offsets + bag);
    int pf_end   = __ldg(offsets + bag + 1);
    int pf_idx   = (lane < pf_end - pf_start) ? __ldg(indices + pf_start + lane) : 0;

    while (bag < num_bags) {
        const int t     = bag >> BAG_SHIFT;          // table id
        const int b     = bag & (N_BAGS_B - 1);      // bag within table
        const int start = pf_start;
        const int end   = pf_end;
        int       myidx = pf_idx;

        // Issue next bag's index/offset loads early so their latency hides
        // under this bag's gather burst.
        const int next_bag = bag + total_warps;
        if (next_bag < num_bags) {
            pf_start = __ldg(offsets + next_bag);
            pf_end   = __ldg(offsets + next_bag + 1);
            pf_idx   = (lane < pf_end - pf_start) ? __ldg(indices + pf_start + lane) : 0;
        }

        // Table base: 64-bit once per bag; per-row offset is 32-bit (<51.2MB).
        const char* __restrict__ wbase =
            wbytes + (long long)t * (N_ROWS * EMB_D * 4ll);

        float4 acc = make_float4(0.f, 0.f, 0.f, 0.f);

        const int n0 = end - start;
        if (n0 == 32) {
            // Hot path: full 32-index bag, fully unrolled -> ptxas batches
            // ~14 independent LDG.E.128 per warp (latency fully hidden).
            #pragma unroll
            for (int j = 0; j < 32; ++j) {
                const unsigned r = (unsigned)__shfl_sync(0xffffffffu, myidx, j);
                const float4 v = __ldg((const float4*)(wbase + (r << 9)));
                acc.x += v.x; acc.y += v.y; acc.z += v.z; acc.w += v.w;
            }
        } else {
            // Generic path: bags longer/shorter than 32.
            int i = start;
            int cur = myidx;
            int n = min(32, end - i);
            while (n > 0) {
                for (int j = 0; j < n; ++j) {
                    const unsigned r = (unsigned)__shfl_sync(0xffffffffu, cur, j);
                    const float4 v = __ldg((const float4*)(wbase + (r << 9)));
                    acc.x += v.x; acc.y += v.y; acc.z += v.z; acc.w += v.w;
                }
                i += n;
                n = min(32, end - i);
                if (n > 0) cur = (lane < n) ? __ldg(indices + i + lane) : 0;
            }
        }

        // Output layout: [B, T*D] feature-concatenated: out[b, t*D + d].
        // Streaming store: zero-reuse output must not displace the active
        // weight-table window in L2.
        float4* __restrict__ o =
            (float4*)(out + ((long long)b * T_TABLES + t) * EMB_D);
        __stcs(o + lane, acc);

        bag = next_bag;
    }
}

extern "C" void kernel_launch(void* const* d_in, const int* in_sizes, int n_in,
                              void* d_out, int out_size)
{
    const int*   indices = (const int*)d_in[0];
    const int*   offsets = (const int*)d_in[1];
    const float* weights = (const float*)d_in[2];
    float*       out     = (float*)d_out;

    emb_bag_kernel<<<CTAS, THREADS>>>(indices, offsets, weights, out);
}